// round 5
// baseline (speedup 1.0000x reference)
#include <cuda_runtime.h>
#include <math.h>

// ---------------------------------------------------------------------------
// RandomProjection: out[b,o] = mean_s( cos(x[b,s,:], p[o,:]) )
//   kernel 1: m[b,:] = mean_s(x[b,s,:]/max(||x||,eps))  + p-norm precompute
//   kernel 2: register-tiled GEMM out = m . p^T * rpn, k-split 4 + ticket
// ---------------------------------------------------------------------------

#define B_    32
#define S_    512
#define D_    768
#define O_    2048
#define EPS_  1e-8f
#define PQ_   4
#define PITCH 196     // padded smem row pitch (floats): conflict-free

__device__ float g_part[PQ_ * B_ * D_];  // x partials (race-free)
__device__ float g_m[B_ * D_];           // combined mean
__device__ float g_rpn[O_];              // 1/max(||p_o||,eps)
__device__ float g_op[4 * B_ * O_];      // gemm k-split partials (race-free)
__device__ int   g_ticket[B_];           // kernel1 tickets (zero-init, self-reset)
__device__ int   g_tick2[O_ / 32];       // kernel2 tickets per o-tile

// ---- packed f32x2 helpers --------------------------------------------------
__device__ __forceinline__ void fma2(unsigned long long& d,
                                     unsigned long long a,
                                     unsigned long long b) {
    asm("fma.rn.f32x2 %0, %1, %2, %3;" : "=l"(d) : "l"(a), "l"(b), "l"(d));
}
__device__ __forceinline__ float unpack_sum(unsigned long long v) {
    float lo, hi;
    asm("mov.b64 {%0, %1}, %2;" : "=f"(lo), "=f"(hi) : "l"(v));
    return lo + hi;
}

// ---------------------------------------------------------------------------
// Kernel 1: blocks 0..127: x normalize+reduce (b,quarter); ticket combine.
//           blocks 128..143: p-norm precompute (128 o-rows per block).
// ---------------------------------------------------------------------------
__global__ void __launch_bounds__(512, 1)
reduce_x_kernel(const float* __restrict__ x, const float* __restrict__ p) {
    const int warp = threadIdx.x >> 5;
    const int lane = threadIdx.x & 31;

    if (blockIdx.x >= 128) {
        // ---- p-norms: 16 warps x 8 rows = 128 rows per block
        const int row0 = (blockIdx.x - 128) * 128 + warp * 8;
        #pragma unroll 1
        for (int r = 0; r < 8; r++) {
            const int o = row0 + r;
            const float4* prow = reinterpret_cast<const float4*>(p + (size_t)o * D_);
            float ss = 0.f;
            #pragma unroll
            for (int c = 0; c < 6; c++) {
                const float4 v = prow[lane + 32 * c];
                ss += v.x * v.x + v.y * v.y + v.z * v.z + v.w * v.w;
            }
            #pragma unroll
            for (int off = 16; off > 0; off >>= 1)
                ss += __shfl_xor_sync(0xFFFFFFFFu, ss, off);
            if (lane == 0) g_rpn[o] = 1.0f / fmaxf(sqrtf(ss), EPS_);
        }
        return;
    }

    __shared__ float4 sm[16 * 192];   // 48 KB
    __shared__ int is_last;

    const int q = blockIdx.x & 3;
    const int b = blockIdx.x >> 2;

    const float4* base = reinterpret_cast<const float4*>(
        x + ((size_t)b * S_ + (size_t)q * 128 + (size_t)warp * 8) * D_);

    const float inv_S = 1.0f / (float)S_;

    float4 acc[6];
    #pragma unroll
    for (int c = 0; c < 6; c++) acc[c] = make_float4(0.f, 0.f, 0.f, 0.f);

    float4 v[6];
    #pragma unroll
    for (int c = 0; c < 6; c++) v[c] = base[lane + 32 * c];

    #pragma unroll
    for (int r = 0; r < 8; r++) {
        float4 vn[6];
        if (r < 7) {
            #pragma unroll
            for (int c = 0; c < 6; c++)
                vn[c] = base[(r + 1) * 192 + lane + 32 * c];
        }

        float ss = 0.f;
        #pragma unroll
        for (int c = 0; c < 6; c++)
            ss += v[c].x * v[c].x + v[c].y * v[c].y
                + v[c].z * v[c].z + v[c].w * v[c].w;
        #pragma unroll
        for (int off = 16; off > 0; off >>= 1)
            ss += __shfl_xor_sync(0xFFFFFFFFu, ss, off);

        const float scale = inv_S / fmaxf(sqrtf(ss), EPS_);

        #pragma unroll
        for (int c = 0; c < 6; c++) {
            acc[c].x += v[c].x * scale;
            acc[c].y += v[c].y * scale;
            acc[c].z += v[c].z * scale;
            acc[c].w += v[c].w * scale;
        }

        if (r < 7) {
            #pragma unroll
            for (int c = 0; c < 6; c++) v[c] = vn[c];
        }
    }

    #pragma unroll
    for (int c = 0; c < 6; c++)
        sm[warp * 192 + lane + 32 * c] = acc[c];
    __syncthreads();

    if (threadIdx.x < 192) {
        float4 s = sm[threadIdx.x];
        #pragma unroll
        for (int w = 1; w < 16; w++) {
            const float4 t = sm[w * 192 + threadIdx.x];
            s.x += t.x; s.y += t.y; s.z += t.z; s.w += t.w;
        }
        reinterpret_cast<float4*>(g_part)[((q * B_ + b) * 192) + threadIdx.x] = s;
    }

    __threadfence();
    __syncthreads();
    if (threadIdx.x == 0)
        is_last = (atomicAdd(&g_ticket[b], 1) == 3) ? 1 : 0;
    __syncthreads();

    if (is_last) {
        __threadfence();
        if (threadIdx.x < 192) {
            const float4* gp = reinterpret_cast<const float4*>(g_part);
            float4 a  = gp[(0 * B_ + b) * 192 + threadIdx.x];
            const float4 b4 = gp[(1 * B_ + b) * 192 + threadIdx.x];
            const float4 c4 = gp[(2 * B_ + b) * 192 + threadIdx.x];
            const float4 d4 = gp[(3 * B_ + b) * 192 + threadIdx.x];
            a.x += b4.x + c4.x + d4.x;
            a.y += b4.y + c4.y + d4.y;
            a.z += b4.z + c4.z + d4.z;
            a.w += b4.w + c4.w + d4.w;
            reinterpret_cast<float4*>(g_m)[b * 192 + threadIdx.x] = a;
        }
        if (threadIdx.x == 0) g_ticket[b] = 0;
    }
}

// ---------------------------------------------------------------------------
// Kernel 2: register-tiled GEMM with k-split.
// Grid: 256 = 64 o-tiles(32 o) x 4 k-quarters(192). Block 256 threads.
// Warp(8) = (bg 0..1, og 0..3): tile 16b x 8o. Lane = (i 0..7, j 0..3): 2b x 2o.
// Each lane accumulates full dots over its k-quarter; no cross-lane reduce.
// Last block per o-tile combines 4 partials and scales by g_rpn.
// ---------------------------------------------------------------------------
__global__ void __launch_bounds__(256, 2)
gemm_kernel(const float* __restrict__ p, float* __restrict__ out) {
    __shared__ float ms[32 * PITCH];   // 24.5 KB
    __shared__ float ps[32 * PITCH];   // 24.5 KB
    __shared__ int is_last;

    const int kq = blockIdx.x & 3;
    const int ot = blockIdx.x >> 2;    // 0..63
    const int tid = threadIdx.x;
    const int k0 = kq * 192;

    // stage m[32][192] and p[ot*32 .. +32][192] (padded rows)
    for (int i = tid; i < 32 * 48; i += 256) {
        const int row = i / 48;
        const int col = (i - row * 48) * 4;
        const float4 mv4 = *reinterpret_cast<const float4*>(
            g_m + (size_t)row * D_ + k0 + col);
        *reinterpret_cast<float4*>(&ms[row * PITCH + col]) = mv4;
        const float4 pv4 = *reinterpret_cast<const float4*>(
            p + (size_t)(ot * 32 + row) * D_ + k0 + col);
        *reinterpret_cast<float4*>(&ps[row * PITCH + col]) = pv4;
    }
    __syncthreads();

    const int warp = tid >> 5;
    const int lane = tid & 31;
    const int bg = warp >> 2;                 // 0..1
    const int og = warp & 3;                  // 0..3
    const int i8 = lane >> 2;                 // 0..7
    const int j4 = lane & 3;                  // 0..3
    const int brow = bg * 16 + 2 * i8;        // local b row (== global b)
    const int orow = og * 8 + 2 * j4;         // local o row within tile

    const float* m0 = &ms[brow * PITCH];
    const float* m1 = &ms[(brow + 1) * PITCH];
    const float* q0 = &ps[orow * PITCH];
    const float* q1 = &ps[(orow + 1) * PITCH];

    unsigned long long a00 = 0ull, a01 = 0ull, a10 = 0ull, a11 = 0ull;

    #pragma unroll 4
    for (int kk = 0; kk < 48; kk++) {
        const ulonglong2 mv0 = *reinterpret_cast<const ulonglong2*>(m0 + kk * 4);
        const ulonglong2 mv1 = *reinterpret_cast<const ulonglong2*>(m1 + kk * 4);
        const ulonglong2 pv0 = *reinterpret_cast<const ulonglong2*>(q0 + kk * 4);
        const ulonglong2 pv1 = *reinterpret_cast<const ulonglong2*>(q1 + kk * 4);
        fma2(a00, mv0.x, pv0.x);  fma2(a00, mv0.y, pv0.y);
        fma2(a01, mv0.x, pv1.x);  fma2(a01, mv0.y, pv1.y);
        fma2(a10, mv1.x, pv0.x);  fma2(a10, mv1.y, pv0.y);
        fma2(a11, mv1.x, pv1.x);  fma2(a11, mv1.y, pv1.y);
    }

    // write k-quarter partials (race-free per kq)
    {
        float* gp = g_op + ((size_t)kq * B_ + brow) * O_ + (ot * 32 + orow);
        *reinterpret_cast<float2*>(gp)      = make_float2(unpack_sum(a00), unpack_sum(a01));
        *reinterpret_cast<float2*>(gp + O_) = make_float2(unpack_sum(a10), unpack_sum(a11));
    }

    __threadfence();
    __syncthreads();
    if (tid == 0)
        is_last = (atomicAdd(&g_tick2[ot], 1) == 3) ? 1 : 0;
    __syncthreads();

    if (is_last) {
        __threadfence();
        // combine 4 partials for this o-tile: 32 b x 32 o = 1024 outputs
        for (int i = tid; i < 32 * 32; i += 256) {
            const int b  = i >> 5;
            const int oo = i & 31;
            const int o  = ot * 32 + oo;
            const size_t idx = (size_t)b * O_ + o;
            float s = g_op[(0 * B_) * O_ + idx] + g_op[((size_t)1 * B_) * O_ + idx]
                    + g_op[((size_t)2 * B_) * O_ + idx] + g_op[((size_t)3 * B_) * O_ + idx];
            out[idx] = s * g_rpn[o];
        }
        if (tid == 0) g_tick2[ot] = 0;
    }
}

// ---------------------------------------------------------------------------
extern "C" void kernel_launch(void* const* d_in, const int* in_sizes, int n_in,
                              void* d_out, int out_size) {
    const float* x = (const float*)d_in[0];   // [32, 512, 768]
    const float* p = (const float*)d_in[1];   // [2048, 768]
    float*     out = (float*)d_out;           // [32, 2048]

    (void)in_sizes; (void)n_in; (void)out_size;

    // Kernel 1: x -> g_m (128 blocks) + p-norms (16 blocks)
    reduce_x_kernel<<<128 + 16, 512>>>(x, p);

    // Kernel 2: tiled GEMM, 64 o-tiles x 4 k-quarters
    gemm_kernel<<<256, 256>>>(p, out);
}

// round 6
// speedup vs baseline: 1.0814x; 1.0814x over previous
#include <cuda_runtime.h>
#include <math.h>

// ---------------------------------------------------------------------------
// RandomProjection: out[b,o] = mean_s( cos(x[b,s,:], p[o,:]) )
//   kernel 1: m[b,:] = mean_s(x/||x||) (ticket-combined) + p-norm precompute
//   kernel 2: register-tiled GEMM (4b x 4o lanes), k-split 12 + ticket combine
// ---------------------------------------------------------------------------

#define B_     32
#define S_     512
#define D_     768
#define O_     2048
#define EPS_   1e-8f
#define PQ_    4

#define KSPLIT 12
#define KB     64            // k floats per gemm block
#define OTILE  64            // o rows per gemm block
#define NOT_   (O_ / OTILE)  // 32 o-tiles
#define PM     68            // smem pitch (floats), conflict-free

__device__ float g_part[PQ_ * B_ * D_];       // x partials (race-free)
__device__ float g_m[B_ * D_];                // combined mean
__device__ float g_rpn[O_];                   // 1/max(||p_o||,eps)
__device__ float g_op[NOT_ * KSPLIT * B_ * OTILE]; // gemm k-split partials
__device__ int   g_ticket[B_];                // kernel1 tickets
__device__ int   g_tick2[NOT_];               // kernel2 tickets

// ---- packed f32x2 helpers --------------------------------------------------
__device__ __forceinline__ void fma2(unsigned long long& d,
                                     unsigned long long a,
                                     unsigned long long b) {
    asm("fma.rn.f32x2 %0, %1, %2, %3;" : "=l"(d) : "l"(a), "l"(b), "l"(d));
}
__device__ __forceinline__ float unpack_sum(unsigned long long v) {
    float lo, hi;
    asm("mov.b64 {%0, %1}, %2;" : "=f"(lo), "=f"(hi) : "l"(v));
    return lo + hi;
}

// ---------------------------------------------------------------------------
// Kernel 1 (unchanged from R5): x reduce (128 blocks) + p-norms (16 blocks)
// ---------------------------------------------------------------------------
__global__ void __launch_bounds__(512, 1)
reduce_x_kernel(const float* __restrict__ x, const float* __restrict__ p) {
    const int warp = threadIdx.x >> 5;
    const int lane = threadIdx.x & 31;

    if (blockIdx.x >= 128) {
        const int row0 = (blockIdx.x - 128) * 128 + warp * 8;
        #pragma unroll 1
        for (int r = 0; r < 8; r++) {
            const int o = row0 + r;
            const float4* prow = reinterpret_cast<const float4*>(p + (size_t)o * D_);
            float ss = 0.f;
            #pragma unroll
            for (int c = 0; c < 6; c++) {
                const float4 v = prow[lane + 32 * c];
                ss += v.x * v.x + v.y * v.y + v.z * v.z + v.w * v.w;
            }
            #pragma unroll
            for (int off = 16; off > 0; off >>= 1)
                ss += __shfl_xor_sync(0xFFFFFFFFu, ss, off);
            if (lane == 0) g_rpn[o] = 1.0f / fmaxf(sqrtf(ss), EPS_);
        }
        return;
    }

    __shared__ float4 sm[16 * 192];
    __shared__ int is_last;

    const int q = blockIdx.x & 3;
    const int b = blockIdx.x >> 2;

    const float4* base = reinterpret_cast<const float4*>(
        x + ((size_t)b * S_ + (size_t)q * 128 + (size_t)warp * 8) * D_);

    const float inv_S = 1.0f / (float)S_;

    float4 acc[6];
    #pragma unroll
    for (int c = 0; c < 6; c++) acc[c] = make_float4(0.f, 0.f, 0.f, 0.f);

    float4 v[6];
    #pragma unroll
    for (int c = 0; c < 6; c++) v[c] = base[lane + 32 * c];

    #pragma unroll
    for (int r = 0; r < 8; r++) {
        float4 vn[6];
        if (r < 7) {
            #pragma unroll
            for (int c = 0; c < 6; c++)
                vn[c] = base[(r + 1) * 192 + lane + 32 * c];
        }
        float ss = 0.f;
        #pragma unroll
        for (int c = 0; c < 6; c++)
            ss += v[c].x * v[c].x + v[c].y * v[c].y
                + v[c].z * v[c].z + v[c].w * v[c].w;
        #pragma unroll
        for (int off = 16; off > 0; off >>= 1)
            ss += __shfl_xor_sync(0xFFFFFFFFu, ss, off);

        const float scale = inv_S / fmaxf(sqrtf(ss), EPS_);
        #pragma unroll
        for (int c = 0; c < 6; c++) {
            acc[c].x += v[c].x * scale;
            acc[c].y += v[c].y * scale;
            acc[c].z += v[c].z * scale;
            acc[c].w += v[c].w * scale;
        }
        if (r < 7) {
            #pragma unroll
            for (int c = 0; c < 6; c++) v[c] = vn[c];
        }
    }

    #pragma unroll
    for (int c = 0; c < 6; c++)
        sm[warp * 192 + lane + 32 * c] = acc[c];
    __syncthreads();

    if (threadIdx.x < 192) {
        float4 s = sm[threadIdx.x];
        #pragma unroll
        for (int w = 1; w < 16; w++) {
            const float4 t = sm[w * 192 + threadIdx.x];
            s.x += t.x; s.y += t.y; s.z += t.z; s.w += t.w;
        }
        reinterpret_cast<float4*>(g_part)[((q * B_ + b) * 192) + threadIdx.x] = s;
    }

    __threadfence();
    __syncthreads();
    if (threadIdx.x == 0)
        is_last = (atomicAdd(&g_ticket[b], 1) == 3) ? 1 : 0;
    __syncthreads();

    if (is_last) {
        __threadfence();
        if (threadIdx.x < 192) {
            const float4* gp = reinterpret_cast<const float4*>(g_part);
            float4 a  = gp[(0 * B_ + b) * 192 + threadIdx.x];
            const float4 b4 = gp[(1 * B_ + b) * 192 + threadIdx.x];
            const float4 c4 = gp[(2 * B_ + b) * 192 + threadIdx.x];
            const float4 d4 = gp[(3 * B_ + b) * 192 + threadIdx.x];
            a.x += b4.x + c4.x + d4.x;
            a.y += b4.y + c4.y + d4.y;
            a.z += b4.z + c4.z + d4.z;
            a.w += b4.w + c4.w + d4.w;
            reinterpret_cast<float4*>(g_m)[b * 192 + threadIdx.x] = a;
        }
        if (threadIdx.x == 0) g_ticket[b] = 0;
    }
}

// ---------------------------------------------------------------------------
// Kernel 2: register-tiled GEMM.
// Grid: 384 = 32 o-tiles x 12 k-splits. Block: 128 threads (4 warps).
// Warp (bg,og in 2x2): tile 16b x 32o. Lane (i = l>>3 in 0..3, j = l&7):
//   b rows: bg*16 + i + 4*rr (rr 0..3), o rows: og*32 + j + 8*ss (ss 0..3).
// 16 f32x2 accumulators; 8 LDS.128 -> 32 fma2 per 4-k step; 2-stage prefetch.
// Last block per o-tile combines 12 partials and scales by g_rpn.
// ---------------------------------------------------------------------------
__global__ void __launch_bounds__(128, 4)
gemm_kernel(const float* __restrict__ p, float* __restrict__ out) {
    __shared__ float msm[B_ * PM];      // 32 x 68 floats ≈ 8.7 KB
    __shared__ float psm[OTILE * PM];   // 64 x 68 floats ≈ 17.4 KB
    __shared__ int is_last;

    const int kq = blockIdx.x % KSPLIT;
    const int ot = blockIdx.x / KSPLIT;         // 0..31
    const int tid = threadIdx.x;
    const int k0 = kq * KB;

    // stage m[32][64] (512 float4) and p[ot*64..+64][64] (1024 float4)
    {
        #pragma unroll
        for (int t = 0; t < 4; t++) {
            const int i = tid + t * 128;        // 0..511
            const int row = i >> 4;
            const int col = (i & 15) * 4;
            const float4 v4 = *reinterpret_cast<const float4*>(
                g_m + (size_t)row * D_ + k0 + col);
            *reinterpret_cast<float4*>(&msm[row * PM + col]) = v4;
        }
        #pragma unroll
        for (int t = 0; t < 8; t++) {
            const int i = tid + t * 128;        // 0..1023
            const int row = i >> 4;
            const int col = (i & 15) * 4;
            const float4 v4 = *reinterpret_cast<const float4*>(
                p + (size_t)(ot * OTILE + row) * D_ + k0 + col);
            *reinterpret_cast<float4*>(&psm[row * PM + col]) = v4;
        }
    }
    __syncthreads();

    const int warp = tid >> 5;
    const int lane = tid & 31;
    const int bg = warp >> 1;            // 0..1
    const int og = warp & 1;             // 0..1
    const int i4 = lane >> 3;            // 0..3
    const int j8 = lane & 7;             // 0..7

    const float* mbase = &msm[(bg * 16 + i4) * PM];       // + 4*rr*PM
    const float* pbase = &psm[(og * 32 + j8) * PM];       // + 8*ss*PM

    unsigned long long acc[4][4];
    #pragma unroll
    for (int rr = 0; rr < 4; rr++)
        #pragma unroll
        for (int ss = 0; ss < 4; ss++) acc[rr][ss] = 0ull;

    ulonglong2 mv[4], pv[4];
    #pragma unroll
    for (int rr = 0; rr < 4; rr++)
        mv[rr] = *reinterpret_cast<const ulonglong2*>(mbase + rr * 4 * PM);
    #pragma unroll
    for (int ss = 0; ss < 4; ss++)
        pv[ss] = *reinterpret_cast<const ulonglong2*>(pbase + ss * 8 * PM);

    #pragma unroll
    for (int kk = 0; kk < 16; kk++) {
        ulonglong2 mn[4], pn[4];
        if (kk < 15) {
            #pragma unroll
            for (int rr = 0; rr < 4; rr++)
                mn[rr] = *reinterpret_cast<const ulonglong2*>(
                    mbase + rr * 4 * PM + (kk + 1) * 4);
            #pragma unroll
            for (int ss = 0; ss < 4; ss++)
                pn[ss] = *reinterpret_cast<const ulonglong2*>(
                    pbase + ss * 8 * PM + (kk + 1) * 4);
        }

        #pragma unroll
        for (int rr = 0; rr < 4; rr++)
            #pragma unroll
            for (int ss = 0; ss < 4; ss++) {
                fma2(acc[rr][ss], mv[rr].x, pv[ss].x);
                fma2(acc[rr][ss], mv[rr].y, pv[ss].y);
            }

        if (kk < 15) {
            #pragma unroll
            for (int rr = 0; rr < 4; rr++) mv[rr] = mn[rr];
            #pragma unroll
            for (int ss = 0; ss < 4; ss++) pv[ss] = pn[ss];
        }
    }

    // write k-split partials: g_op[((ot*KSPLIT + kq)*B_ + b)*OTILE + oo]
    {
        float* gbase = g_op + ((size_t)(ot * KSPLIT + kq) * B_) * OTILE;
        #pragma unroll
        for (int rr = 0; rr < 4; rr++) {
            const int b = bg * 16 + i4 + 4 * rr;
            #pragma unroll
            for (int ss = 0; ss < 4; ss++) {
                const int oo = og * 32 + j8 + 8 * ss;
                gbase[(size_t)b * OTILE + oo] = unpack_sum(acc[rr][ss]);
            }
        }
    }

    __threadfence();
    __syncthreads();
    if (tid == 0)
        is_last = (atomicAdd(&g_tick2[ot], 1) == KSPLIT - 1) ? 1 : 0;
    __syncthreads();

    if (is_last) {
        __threadfence();
        // combine: 32 b x 64 o = 2048 outputs = 512 float4; 4 per thread
        const float4* gp = reinterpret_cast<const float4*>(
            g_op + ((size_t)ot * KSPLIT * B_) * OTILE);
        #pragma unroll
        for (int t = 0; t < 4; t++) {
            const int i = tid + t * 128;        // 0..511 : (b, oo/4)
            float4 s = gp[i];
            #pragma unroll
            for (int k = 1; k < KSPLIT; k++) {
                const float4 v = gp[(size_t)k * B_ * (OTILE / 4) + i];
                s.x += v.x; s.y += v.y; s.z += v.z; s.w += v.w;
            }
            const int b  = i >> 4;
            const int oo = (i & 15) * 4;
            const int o  = ot * OTILE + oo;
            s.x *= g_rpn[o];
            s.y *= g_rpn[o + 1];
            s.z *= g_rpn[o + 2];
            s.w *= g_rpn[o + 3];
            *reinterpret_cast<float4*>(out + (size_t)b * O_ + o) = s;
        }
        if (tid == 0) g_tick2[ot] = 0;
    }
}

// ---------------------------------------------------------------------------
extern "C" void kernel_launch(void* const* d_in, const int* in_sizes, int n_in,
                              void* d_out, int out_size) {
    const float* x = (const float*)d_in[0];   // [32, 512, 768]
    const float* p = (const float*)d_in[1];   // [2048, 768]
    float*     out = (float*)d_out;           // [32, 2048]

    (void)in_sizes; (void)n_in; (void)out_size;

    reduce_x_kernel<<<128 + 16, 512>>>(x, p);
    gemm_kernel<<<NOT_ * KSPLIT, 128>>>(p, out);
}

// round 7
// speedup vs baseline: 1.2600x; 1.1651x over previous
#include <cuda_runtime.h>
#include <math.h>

// ---------------------------------------------------------------------------
// RandomProjection: out[b,o] = mean_s( cos(x[b,s,:], p[o,:]) )
//   kernel 1: m = mean_s(x/||x||) (ticket combine) + p-norms + zero(out)
//   kernel 2: register-tiled GEMM, k-split 8, rpn folded into staged p,
//             atomicAdd epilogue (no tickets, no global partials)
// ---------------------------------------------------------------------------

#define B_     32
#define S_     512
#define D_     768
#define O_     2048
#define EPS_   1e-8f

#define KSPLIT 8
#define KB     96            // k floats per gemm block
#define OTILE  64            // o rows per gemm block
#define NOT_   (O_ / OTILE)  // 32 o-tiles
#define PM     100           // smem pitch (floats): 400B rows, conflict-free

__device__ float g_part[4 * B_ * D_];    // x partials (race-free)
__device__ float g_m[B_ * D_];           // combined mean
__device__ float g_rpn[O_];              // 1/max(||p_o||,eps)
__device__ int   g_ticket[B_];           // kernel1 tickets (zero-init, self-reset)

// ---- packed f32x2 helpers --------------------------------------------------
__device__ __forceinline__ void fma2(unsigned long long& d,
                                     unsigned long long a,
                                     unsigned long long b) {
    asm("fma.rn.f32x2 %0, %1, %2, %3;" : "=l"(d) : "l"(a), "l"(b), "l"(d));
}
__device__ __forceinline__ float unpack_sum(unsigned long long v) {
    float lo, hi;
    asm("mov.b64 {%0, %1}, %2;" : "=f"(lo), "=f"(hi) : "l"(v));
    return lo + hi;
}

// ---------------------------------------------------------------------------
// Kernel 1: blocks 0..127: x normalize+reduce; ticket combine -> g_m.
//           blocks 128..143: p-norms (128 rows each) + zero out-slice.
// ---------------------------------------------------------------------------
__global__ void __launch_bounds__(512, 1)
reduce_x_kernel(const float* __restrict__ x, const float* __restrict__ p,
                float* __restrict__ out) {
    const int warp = threadIdx.x >> 5;
    const int lane = threadIdx.x & 31;

    if (blockIdx.x >= 128) {
        const int blk = blockIdx.x - 128;      // 0..15
        // zero out-slice: 65536 floats / 16 blocks = 1024 float4 per block
        {
            float4* o4 = reinterpret_cast<float4*>(out) + blk * 1024;
            o4[threadIdx.x]       = make_float4(0.f, 0.f, 0.f, 0.f);
            o4[threadIdx.x + 512] = make_float4(0.f, 0.f, 0.f, 0.f);
        }
        // p-norms: 16 warps x 8 rows = 128 rows per block
        const int row0 = blk * 128 + warp * 8;
        #pragma unroll 1
        for (int r = 0; r < 8; r++) {
            const int o = row0 + r;
            const float4* prow = reinterpret_cast<const float4*>(p + (size_t)o * D_);
            float ss = 0.f;
            #pragma unroll
            for (int c = 0; c < 6; c++) {
                const float4 v = prow[lane + 32 * c];
                ss += v.x * v.x + v.y * v.y + v.z * v.z + v.w * v.w;
            }
            #pragma unroll
            for (int off = 16; off > 0; off >>= 1)
                ss += __shfl_xor_sync(0xFFFFFFFFu, ss, off);
            if (lane == 0) g_rpn[o] = 1.0f / fmaxf(sqrtf(ss), EPS_);
        }
        return;
    }

    __shared__ float4 sm[16 * 192];
    __shared__ int is_last;

    const int q = blockIdx.x & 3;
    const int b = blockIdx.x >> 2;

    const float4* base = reinterpret_cast<const float4*>(
        x + ((size_t)b * S_ + (size_t)q * 128 + (size_t)warp * 8) * D_);

    const float inv_S = 1.0f / (float)S_;

    float4 acc[6];
    #pragma unroll
    for (int c = 0; c < 6; c++) acc[c] = make_float4(0.f, 0.f, 0.f, 0.f);

    float4 v[6];
    #pragma unroll
    for (int c = 0; c < 6; c++) v[c] = base[lane + 32 * c];

    #pragma unroll
    for (int r = 0; r < 8; r++) {
        float4 vn[6];
        if (r < 7) {
            #pragma unroll
            for (int c = 0; c < 6; c++)
                vn[c] = base[(r + 1) * 192 + lane + 32 * c];
        }
        float ss = 0.f;
        #pragma unroll
        for (int c = 0; c < 6; c++)
            ss += v[c].x * v[c].x + v[c].y * v[c].y
                + v[c].z * v[c].z + v[c].w * v[c].w;
        #pragma unroll
        for (int off = 16; off > 0; off >>= 1)
            ss += __shfl_xor_sync(0xFFFFFFFFu, ss, off);

        const float scale = inv_S / fmaxf(sqrtf(ss), EPS_);
        #pragma unroll
        for (int c = 0; c < 6; c++) {
            acc[c].x += v[c].x * scale;
            acc[c].y += v[c].y * scale;
            acc[c].z += v[c].z * scale;
            acc[c].w += v[c].w * scale;
        }
        if (r < 7) {
            #pragma unroll
            for (int c = 0; c < 6; c++) v[c] = vn[c];
        }
    }

    #pragma unroll
    for (int c = 0; c < 6; c++)
        sm[warp * 192 + lane + 32 * c] = acc[c];
    __syncthreads();

    if (threadIdx.x < 192) {
        float4 s = sm[threadIdx.x];
        #pragma unroll
        for (int w = 1; w < 16; w++) {
            const float4 t = sm[w * 192 + threadIdx.x];
            s.x += t.x; s.y += t.y; s.z += t.z; s.w += t.w;
        }
        reinterpret_cast<float4*>(g_part)[((q * B_ + b) * 192) + threadIdx.x] = s;
    }

    __threadfence();
    __syncthreads();
    if (threadIdx.x == 0)
        is_last = (atomicAdd(&g_ticket[b], 1) == 3) ? 1 : 0;
    __syncthreads();

    if (is_last) {
        __threadfence();
        if (threadIdx.x < 192) {
            const float4* gp = reinterpret_cast<const float4*>(g_part);
            float4 a  = gp[(0 * B_ + b) * 192 + threadIdx.x];
            const float4 b4 = gp[(1 * B_ + b) * 192 + threadIdx.x];
            const float4 c4 = gp[(2 * B_ + b) * 192 + threadIdx.x];
            const float4 d4 = gp[(3 * B_ + b) * 192 + threadIdx.x];
            a.x += b4.x + c4.x + d4.x;
            a.y += b4.y + c4.y + d4.y;
            a.z += b4.z + c4.z + d4.z;
            a.w += b4.w + c4.w + d4.w;
            reinterpret_cast<float4*>(g_m)[b * 192 + threadIdx.x] = a;
        }
        if (threadIdx.x == 0) g_ticket[b] = 0;
    }
}

// ---------------------------------------------------------------------------
// Kernel 2: register-tiled GEMM, atomicAdd epilogue.
// Grid: 256 = 32 o-tiles x 8 k-splits (single wave, ~5 blocks/SM residency).
// Block: 256 threads = 8 warps. Warp (wb 0..3, wo 0..1): tile 8b x 32o.
// Lane (bi = l>>3 in 0..3, oj = l&7): thread tile 2b x 4o.
//   b = wb*8 + bi*2 + rr (rr 0..1), o = ot*64 + wo*32 + oj + 8*ss (ss 0..3).
// psm is pre-scaled by g_rpn, so accumulators are final -> atomicAdd(out).
// ---------------------------------------------------------------------------
__global__ void __launch_bounds__(256)
gemm_kernel(const float* __restrict__ p, float* __restrict__ out) {
    __shared__ float msm[B_ * PM];      // 32 x 100 floats = 12.8 KB
    __shared__ float psm[OTILE * PM];   // 64 x 100 floats = 25.6 KB

    const int kq  = blockIdx.x & 7;
    const int ot  = blockIdx.x >> 3;    // 0..31
    const int tid = threadIdx.x;
    const int k0  = kq * KB;

    // stage m[32][96] (768 float4) and p[ot*64..+64][96]*rpn (1536 float4)
    #pragma unroll
    for (int t = 0; t < 3; t++) {
        const int i   = tid + t * 256;          // 0..767
        const int row = i / 24;
        const int col = (i - row * 24) * 4;
        const float4 v4 = *reinterpret_cast<const float4*>(
            g_m + (size_t)row * D_ + k0 + col);
        *reinterpret_cast<float4*>(&msm[row * PM + col]) = v4;
    }
    #pragma unroll
    for (int t = 0; t < 6; t++) {
        const int i   = tid + t * 256;          // 0..1535
        const int row = i / 24;
        const int col = (i - row * 24) * 4;
        float4 v4 = *reinterpret_cast<const float4*>(
            p + (size_t)(ot * OTILE + row) * D_ + k0 + col);
        const float rp = g_rpn[ot * OTILE + row];
        v4.x *= rp; v4.y *= rp; v4.z *= rp; v4.w *= rp;
        *reinterpret_cast<float4*>(&psm[row * PM + col]) = v4;
    }
    __syncthreads();

    const int warp = tid >> 5;
    const int lane = tid & 31;
    const int wb = warp >> 1;            // 0..3
    const int wo = warp & 1;             // 0..1
    const int bi = lane >> 3;            // 0..3
    const int oj = lane & 7;             // 0..7

    const float* mb = &msm[(wb * 8 + bi * 2) * PM];
    const float* pb = &psm[(wo * 32 + oj) * PM];

    unsigned long long acc[2][4];
    #pragma unroll
    for (int rr = 0; rr < 2; rr++)
        #pragma unroll
        for (int ss = 0; ss < 4; ss++) acc[rr][ss] = 0ull;

    #pragma unroll
    for (int kk = 0; kk < 24; kk++) {
        const ulonglong2 m0 = *reinterpret_cast<const ulonglong2*>(mb + kk * 4);
        const ulonglong2 m1 = *reinterpret_cast<const ulonglong2*>(mb + PM + kk * 4);
        ulonglong2 pv[4];
        #pragma unroll
        for (int ss = 0; ss < 4; ss++)
            pv[ss] = *reinterpret_cast<const ulonglong2*>(pb + ss * 8 * PM + kk * 4);

        #pragma unroll
        for (int ss = 0; ss < 4; ss++) {
            fma2(acc[0][ss], m0.x, pv[ss].x);
            fma2(acc[0][ss], m0.y, pv[ss].y);
            fma2(acc[1][ss], m1.x, pv[ss].x);
            fma2(acc[1][ss], m1.y, pv[ss].y);
        }
    }

    // epilogue: accumulators are already scaled by rpn -> atomicAdd into out
    #pragma unroll
    for (int rr = 0; rr < 2; rr++) {
        const int b = wb * 8 + bi * 2 + rr;
        #pragma unroll
        for (int ss = 0; ss < 4; ss++) {
            const int o = ot * OTILE + wo * 32 + oj + 8 * ss;
            atomicAdd(out + (size_t)b * O_ + o, unpack_sum(acc[rr][ss]));
        }
    }
}

// ---------------------------------------------------------------------------
extern "C" void kernel_launch(void* const* d_in, const int* in_sizes, int n_in,
                              void* d_out, int out_size) {
    const float* x = (const float*)d_in[0];   // [32, 512, 768]
    const float* p = (const float*)d_in[1];   // [2048, 768]
    float*     out = (float*)d_out;           // [32, 2048]

    (void)in_sizes; (void)n_in; (void)out_size;

    reduce_x_kernel<<<128 + 16, 512>>>(x, p, out);
    gemm_kernel<<<NOT_ * KSPLIT, 256>>>(p, out);
}